// round 3
// baseline (speedup 1.0000x reference)
#include <cuda_runtime.h>
#include <math.h>

// Problem dims
#define BB 32
#define TT 12
#define NN 325
#define DD 128
#define HH 8
#define HDM 16
#define FF 512
#define TOK (BB*TT*NN)   // 124800

// ---------------- scratch (static device memory; no allocs) ----------------
__device__ float g_qkv [(size_t)TOK * 384];
__device__ float g_att [(size_t)TOK * DD];
__device__ float g_proj[(size_t)TOK * DD];
__device__ float g_x1  [(size_t)TOK * DD];
__device__ float g_x2  [(size_t)TOK * DD];
__device__ float g_h   [(size_t)TOK * FF];

// ---------------- helpers ----------------
__device__ __forceinline__ float gelu_tanh(float x) {
    const float k0 = 0.7978845608028654f; // sqrt(2/pi)
    float x3 = x * x * x;
    return 0.5f * x * (1.0f + tanhf(k0 * (x + 0.044715f * x3)));
}

// ---------------- generic tiled GEMM: C[M,N] = A[M,K] @ W[N,K]^T + bias, act ----------------
// BM=BN=64, BK=16, 256 threads, 4x4 per thread. M,N multiples of 64; K multiple of 16.
__global__ void gemm_bias_act(const float* __restrict__ A,
                              const float* __restrict__ W,
                              const float* __restrict__ bias,
                              float* __restrict__ C,
                              int M, int N, int K, int act)
{
    __shared__ float As[16][65];
    __shared__ float Ws[16][65];

    const int tid = threadIdx.x;
    const int bm = blockIdx.x * 64;
    const int bn = blockIdx.y * 64;
    const int tx = tid & 15;         // 0..15
    const int ty = tid >> 4;         // 0..15
    const int lr = tid >> 2;         // 0..63 : tile row for loads
    const int lc = (tid & 3) * 4;    // 0,4,8,12 : k base for loads

    float acc[4][4];
    #pragma unroll
    for (int i = 0; i < 4; i++)
        #pragma unroll
        for (int j = 0; j < 4; j++) acc[i][j] = 0.0f;

    for (int kt = 0; kt < K; kt += 16) {
        float4 av = *(const float4*)&A[(size_t)(bm + lr) * K + kt + lc];
        float4 wv = *(const float4*)&W[(size_t)(bn + lr) * K + kt + lc];
        As[lc + 0][lr] = av.x; As[lc + 1][lr] = av.y;
        As[lc + 2][lr] = av.z; As[lc + 3][lr] = av.w;
        Ws[lc + 0][lr] = wv.x; Ws[lc + 1][lr] = wv.y;
        Ws[lc + 2][lr] = wv.z; Ws[lc + 3][lr] = wv.w;
        __syncthreads();

        #pragma unroll
        for (int k = 0; k < 16; k++) {
            float a[4], w[4];
            #pragma unroll
            for (int i = 0; i < 4; i++) a[i] = As[k][ty * 4 + i];
            #pragma unroll
            for (int j = 0; j < 4; j++) w[j] = Ws[k][tx * 4 + j];
            #pragma unroll
            for (int i = 0; i < 4; i++)
                #pragma unroll
                for (int j = 0; j < 4; j++)
                    acc[i][j] = fmaf(a[i], w[j], acc[i][j]);
        }
        __syncthreads();
    }

    #pragma unroll
    for (int i = 0; i < 4; i++) {
        int row = bm + ty * 4 + i;
        #pragma unroll
        for (int j = 0; j < 4; j++) {
            int col = bn + tx * 4 + j;
            float v = acc[i][j] + bias[col];
            if (act) v = gelu_tanh(v);
            C[(size_t)row * N + col] = v;
        }
    }
}

// ---------------- temporal attention: block per (b, n), all 8 heads, seq T=12 ----------------
__global__ void temporal_attn(const float* __restrict__ qkv, float* __restrict__ att)
{
    const int b = blockIdx.x / NN;
    const int n = blockIdx.x % NN;
    const int tid = threadIdx.x;

    __shared__ float s_qkv[TT][384];
    __shared__ float s_p[HH][TT][TT];

    // load qkv rows for the 12 timesteps of this (b, n)
    for (int e = tid; e < TT * 384; e += 256) {
        int t = e / 384, c = e % 384;
        s_qkv[t][c] = qkv[((size_t)((b * TT + t) * NN + n)) * 384 + c];
    }
    __syncthreads();

    // scores
    for (int e = tid; e < HH * TT * TT; e += 256) {
        int h = e / (TT * TT);
        int r = (e / TT) % TT;
        int c = e % TT;
        float s = 0.0f;
        #pragma unroll
        for (int d = 0; d < HDM; d++)
            s = fmaf(s_qkv[r][h * HDM + d], s_qkv[c][128 + h * HDM + d], s);
        s_p[h][r][c] = s * 0.25f;
    }
    __syncthreads();

    // softmax per (h, r)
    if (tid < HH * TT) {
        int h = tid / TT, r = tid % TT;
        float m = -INFINITY;
        #pragma unroll
        for (int c = 0; c < TT; c++) m = fmaxf(m, s_p[h][r][c]);
        float sum = 0.0f;
        #pragma unroll
        for (int c = 0; c < TT; c++) {
            float p = expf(s_p[h][r][c] - m);
            s_p[h][r][c] = p;
            sum += p;
        }
        float inv = 1.0f / sum;
        #pragma unroll
        for (int c = 0; c < TT; c++) s_p[h][r][c] *= inv;
    }
    __syncthreads();

    // out = P @ V
    for (int e = tid; e < HH * TT * HDM; e += 256) {
        int h = e / (TT * HDM);
        int r = (e / HDM) % TT;
        int d = e % HDM;
        float o = 0.0f;
        #pragma unroll
        for (int c = 0; c < TT; c++)
            o = fmaf(s_p[h][r][c], s_qkv[c][256 + h * HDM + d], o);
        att[((size_t)((b * TT + r) * NN + n)) * DD + h * HDM + d] = o;
    }
}

// ---------------- spatial attention: block per (bt, h), seq N=325, bias ----------------
__global__ void spatial_attn(const float* __restrict__ qkv,
                             const float* __restrict__ bias,
                             float* __restrict__ att)
{
    const int bt = blockIdx.x / HH;
    const int h  = blockIdx.x % HH;
    const int tid = threadIdx.x;
    const int warp = tid >> 5;
    const int lane = tid & 31;

    __shared__ float s_k[NN][17];
    __shared__ float s_v[NN][17];

    for (int e = tid; e < NN * HDM; e += 256) {
        int n = e / HDM, d = e % HDM;
        const float* row = qkv + ((size_t)(bt * NN + n)) * 384;
        s_k[n][d] = row[128 + h * HDM + d];
        s_v[n][d] = row[256 + h * HDM + d];
    }
    __syncthreads();

    for (int qi = warp; qi < NN; qi += 8) {
        const float* qrow = qkv + ((size_t)(bt * NN + qi)) * 384 + h * HDM;
        float q[HDM];
        #pragma unroll
        for (int d = 0; d < HDM; d++) q[d] = qrow[d];   // broadcast loads

        float s[11];
        float m = -INFINITY;
        #pragma unroll
        for (int i = 0; i < 11; i++) {
            int j = lane + 32 * i;
            if (j < NN) {
                float a = 0.0f;
                #pragma unroll
                for (int d = 0; d < HDM; d++) a = fmaf(q[d], s_k[j][d], a);
                s[i] = a * 0.25f + bias[qi * NN + j];
            } else {
                s[i] = -INFINITY;
            }
            m = fmaxf(m, s[i]);
        }
        #pragma unroll
        for (int o = 16; o; o >>= 1) m = fmaxf(m, __shfl_xor_sync(0xffffffffu, m, o));

        float p[11];
        float sum = 0.0f;
        #pragma unroll
        for (int i = 0; i < 11; i++) { p[i] = expf(s[i] - m); sum += p[i]; }
        #pragma unroll
        for (int o = 16; o; o >>= 1) sum += __shfl_xor_sync(0xffffffffu, sum, o);
        float inv = 1.0f / sum;

        float acc[HDM];
        #pragma unroll
        for (int d = 0; d < HDM; d++) acc[d] = 0.0f;
        #pragma unroll
        for (int i = 0; i < 11; i++) {
            int j = lane + 32 * i;
            if (j < NN) {
                #pragma unroll
                for (int d = 0; d < HDM; d++) acc[d] = fmaf(p[i], s_v[j][d], acc[d]);
            }
        }
        #pragma unroll
        for (int d = 0; d < HDM; d++)
            #pragma unroll
            for (int o = 16; o; o >>= 1)
                acc[d] += __shfl_xor_sync(0xffffffffu, acc[d], o);

        if (lane < HDM) {
            float myv = 0.0f;
            #pragma unroll
            for (int d = 0; d < HDM; d++) if (lane == d) myv = acc[d];
            att[((size_t)(bt * NN + qi)) * DD + h * HDM + lane] = myv * inv;
        }
    }
}

// ---------------- residual + layernorm: warp per token (D=128, 4 per lane) ----------------
__global__ void add_ln(const float* __restrict__ x, const float* __restrict__ r,
                       const float* __restrict__ g, const float* __restrict__ b,
                       float* __restrict__ out)
{
    const int warp = threadIdx.x >> 5;
    const int lane = threadIdx.x & 31;
    const size_t tok = (size_t)blockIdx.x * 8 + warp;

    const float4 xv = ((const float4*)x)[tok * 32 + lane];
    const float4 rv = ((const float4*)r)[tok * 32 + lane];
    float v0 = xv.x + rv.x, v1 = xv.y + rv.y, v2 = xv.z + rv.z, v3 = xv.w + rv.w;

    float sum = v0 + v1 + v2 + v3;
    float sq  = v0*v0 + v1*v1 + v2*v2 + v3*v3;
    #pragma unroll
    for (int o = 16; o; o >>= 1) {
        sum += __shfl_xor_sync(0xffffffffu, sum, o);
        sq  += __shfl_xor_sync(0xffffffffu, sq, o);
    }
    float mean = sum * (1.0f / 128.0f);
    float var  = sq * (1.0f / 128.0f) - mean * mean;
    float rstd = rsqrtf(var + 1e-5f);

    const float4 gv = ((const float4*)g)[lane];
    const float4 bv = ((const float4*)b)[lane];
    float4 ov;
    ov.x = (v0 - mean) * rstd * gv.x + bv.x;
    ov.y = (v1 - mean) * rstd * gv.y + bv.y;
    ov.z = (v2 - mean) * rstd * gv.z + bv.z;
    ov.w = (v3 - mean) * rstd * gv.w + bv.w;
    ((float4*)out)[tok * 32 + lane] = ov;
}

// ---------------- launcher ----------------
extern "C" void kernel_launch(void* const* d_in, const int* in_sizes, int n_in,
                              void* d_out, int out_size)
{
    const float* x        = (const float*)d_in[0];
    const float* t_w_in   = (const float*)d_in[1];
    const float* t_b_in   = (const float*)d_in[2];
    const float* t_w_out  = (const float*)d_in[3];
    const float* t_b_out  = (const float*)d_in[4];
    const float* s_w_in   = (const float*)d_in[5];
    const float* s_b_in   = (const float*)d_in[6];
    const float* s_w_out  = (const float*)d_in[7];
    const float* s_b_out  = (const float*)d_in[8];
    const float* gbias    = (const float*)d_in[9];
    const float* norm_t_g = (const float*)d_in[10];
    const float* norm_t_b = (const float*)d_in[11];
    const float* norm_s_g = (const float*)d_in[12];
    const float* norm_s_b = (const float*)d_in[13];
    const float* ff_w1    = (const float*)d_in[14];
    const float* ff_b1    = (const float*)d_in[15];
    const float* ff_w2    = (const float*)d_in[16];
    const float* ff_b2    = (const float*)d_in[17];
    const float* norm_f_g = (const float*)d_in[18];
    const float* norm_f_b = (const float*)d_in[19];
    float* out = (float*)d_out;

    float *qkv, *att, *proj, *x1, *x2, *hbuf;
    cudaGetSymbolAddress((void**)&qkv,  g_qkv);
    cudaGetSymbolAddress((void**)&att,  g_att);
    cudaGetSymbolAddress((void**)&proj, g_proj);
    cudaGetSymbolAddress((void**)&x1,   g_x1);
    cudaGetSymbolAddress((void**)&x2,   g_x2);
    cudaGetSymbolAddress((void**)&hbuf, g_h);

    dim3 blk(256);

    // --- temporal attention ---
    gemm_bias_act<<<dim3(TOK/64, 384/64), blk>>>(x, t_w_in, t_b_in, qkv, TOK, 384, 128, 0);
    temporal_attn<<<BB * NN, blk>>>(qkv, att);
    gemm_bias_act<<<dim3(TOK/64, 128/64), blk>>>(att, t_w_out, t_b_out, proj, TOK, 128, 128, 0);
    add_ln<<<TOK/8, blk>>>(x, proj, norm_t_g, norm_t_b, x1);

    // --- spatial attention (with graph bias) ---
    gemm_bias_act<<<dim3(TOK/64, 384/64), blk>>>(x1, s_w_in, s_b_in, qkv, TOK, 384, 128, 0);
    spatial_attn<<<BB * TT * HH, blk>>>(qkv, gbias, att);
    gemm_bias_act<<<dim3(TOK/64, 128/64), blk>>>(att, s_w_out, s_b_out, proj, TOK, 128, 128, 0);
    add_ln<<<TOK/8, blk>>>(x1, proj, norm_s_g, norm_s_b, x2);

    // --- FFN ---
    gemm_bias_act<<<dim3(TOK/64, 512/64), blk>>>(x2, ff_w1, ff_b1, hbuf, TOK, 512, 128, 1);
    gemm_bias_act<<<dim3(TOK/64, 128/64), blk>>>(hbuf, ff_w2, ff_b2, proj, TOK, 128, 512, 0);
    add_ln<<<TOK/8, blk>>>(x2, proj, norm_f_g, norm_f_b, out);
}